// round 1
// baseline (speedup 1.0000x reference)
#include <cuda_runtime.h>

// LWTA: within each group of 4 consecutive floats, keep only the (first) max,
// zero the rest. Input [4096, 8192] fp32 -> output same shape.
// One thread per group of 4 => one float4 load + one float4 store, fully
// coalesced. Pure HBM-streaming kernel.

__global__ void lwta_kernel(const float4* __restrict__ in,
                            float4* __restrict__ out,
                            int n_groups) {
    int g = blockIdx.x * blockDim.x + threadIdx.x;
    if (g >= n_groups) return;

    float4 v = in[g];

    // argmax with first-max-wins semantics (matches jnp.argmax / torch .max):
    // element i wins iff v_i > all earlier elements and >= all later elements.
    float m = v.x;
    int widx = 0;
    if (v.y > m) { m = v.y; widx = 1; }
    if (v.z > m) { m = v.z; widx = 2; }
    if (v.w > m) { m = v.w; widx = 3; }

    float4 r;
    r.x = (widx == 0) ? v.x : 0.0f;
    r.y = (widx == 1) ? v.y : 0.0f;
    r.z = (widx == 2) ? v.z : 0.0f;
    r.w = (widx == 3) ? v.w : 0.0f;

    out[g] = r;
}

extern "C" void kernel_launch(void* const* d_in, const int* in_sizes, int n_in,
                              void* d_out, int out_size) {
    const float4* in = (const float4*)d_in[0];
    float4* out = (float4*)d_out;
    int n_elems = in_sizes[0];          // 4096*8192 = 33554432
    int n_groups = n_elems / 4;         // 8388608 groups, one float4 each

    const int threads = 256;
    int blocks = (n_groups + threads - 1) / threads;
    lwta_kernel<<<blocks, threads>>>(in, out, n_groups);
}

// round 2
// speedup vs baseline: 1.0101x; 1.0101x over previous
#include <cuda_runtime.h>

// LWTA over groups of 4 consecutive fp32. Pure HBM-streaming kernel.
// R2: 4 float4 groups per thread, loads batched front-to-back for MLP=4
// (hide DRAM latency), stores batched after. Block-tiled so every load/store
// sweep is fully coalesced.

#define GROUPS_PER_THREAD 4

__global__ void lwta_kernel(const float4* __restrict__ in,
                            float4* __restrict__ out,
                            int n_groups) {
    int tile = blockIdx.x * blockDim.x * GROUPS_PER_THREAD;
    int tid = threadIdx.x;

    float4 v[GROUPS_PER_THREAD];
    int idx[GROUPS_PER_THREAD];

    // Front-batched independent loads -> MLP = GROUPS_PER_THREAD
#pragma unroll
    for (int k = 0; k < GROUPS_PER_THREAD; k++) {
        idx[k] = tile + tid + k * blockDim.x;
        if (idx[k] < n_groups) v[k] = in[idx[k]];
    }

#pragma unroll
    for (int k = 0; k < GROUPS_PER_THREAD; k++) {
        float4 x = v[k];
        // argmax with first-max-wins (strict >), matching jnp.argmax
        float m = x.x;
        int w = 0;
        if (x.y > m) { m = x.y; w = 1; }
        if (x.z > m) { m = x.z; w = 2; }
        if (x.w > m) { m = x.w; w = 3; }
        float4 r;
        r.x = (w == 0) ? x.x : 0.0f;
        r.y = (w == 1) ? x.y : 0.0f;
        r.z = (w == 2) ? x.z : 0.0f;
        r.w = (w == 3) ? x.w : 0.0f;
        v[k] = r;
    }

#pragma unroll
    for (int k = 0; k < GROUPS_PER_THREAD; k++) {
        if (idx[k] < n_groups) out[idx[k]] = v[k];
    }
}

extern "C" void kernel_launch(void* const* d_in, const int* in_sizes, int n_in,
                              void* d_out, int out_size) {
    const float4* in = (const float4*)d_in[0];
    float4* out = (float4*)d_out;
    int n_elems = in_sizes[0];              // 4096*8192
    int n_groups = n_elems / 4;             // 8388608

    const int threads = 256;
    int groups_per_block = threads * GROUPS_PER_THREAD;
    int blocks = (n_groups + groups_per_block - 1) / groups_per_block;  // 8192
    lwta_kernel<<<blocks, threads>>>(in, out, n_groups);
}